// round 14
// baseline (speedup 1.0000x reference)
#include <cuda_runtime.h>
#include <cuda_bf16.h>
#include <math.h>
#include <cstdint>

#define IT 20
#define NB 4
#define GH 480
#define GW 640
#define SH 120
#define SW 160
#define NC 32

typedef unsigned long long u64;

// ---------------- static device scratch (no runtime allocation) ----------------
__device__ uint32_t g_xtb[NB*GH*GW*16];             // x transposed to NHWC bf16x2 (78 MB)
__device__ uint32_t g_dtb[NB*SH*SW*16];             // d transposed to NHWC bf16x2 (4.9 MB)
__device__ float    g_rg[IT*NB*SH*SW];              // pooled gt
__device__ float    g_ixb[IT*NB*SH*SW];             // sample x pixel coord
__device__ float    g_iyb[IT*NB*SH*SW];             // sample y pixel coord
__device__ uint32_t g_feat[IT*NB*SH*SW*16];         // sampled features NHWC bf16x2 (98 MB)
__device__ uint32_t g_attd[IT*NB*SH*SW*16];         // sigmoid(conv)*d NHWC bf16x2  (98 MB)
__device__ float    g_num[IT];
__device__ float    g_den[IT];

// ---------------- helpers ----------------
__device__ __forceinline__ uint32_t pack_bf16(float lo, float hi) {
    uint32_t r;
    asm("cvt.rn.bf16x2.f32 %0, %1, %2;" : "=r"(r) : "f"(hi), "f"(lo));
    return r;
}
__device__ __forceinline__ float2 unpack_bf16(uint32_t u) {
    __nv_bfloat162 h = *reinterpret_cast<const __nv_bfloat162*>(&u);
    return make_float2(__bfloat162float(h.x), __bfloat162float(h.y));
}
__device__ __forceinline__ uint32_t smem_to_u32(const void* p) {
    uint32_t a;
    asm("{ .reg .u64 t; cvta.to.shared.u64 t, %1; cvt.u32.u64 %0, t; }" : "=r"(a) : "l"(p));
    return a;
}
__device__ __forceinline__ void ldmatrix_x4(uint32_t* r, uint32_t addr) {
    asm volatile("ldmatrix.sync.aligned.m8n8.x4.shared.b16 {%0, %1, %2, %3}, [%4];"
        : "=r"(r[0]), "=r"(r[1]), "=r"(r[2]), "=r"(r[3]) : "r"(addr));
}
__device__ __forceinline__ void mma_bf16(float* c, const uint32_t* a, const uint32_t* b) {
    asm volatile("mma.sync.aligned.m16n8k16.row.col.f32.bf16.bf16.f32 "
        "{%0, %1, %2, %3}, {%4, %5, %6, %7}, {%8, %9}, {%0, %1, %2, %3};"
        : "+f"(c[0]), "+f"(c[1]), "+f"(c[2]), "+f"(c[3])
        : "r"(a[0]), "r"(a[1]), "r"(a[2]), "r"(a[3]), "r"(b[0]), "r"(b[1]));
}

// ---------------- zero per-iteration accumulators ----------------
__global__ void zero_kernel() {
    int t = threadIdx.x;
    if (t < IT) { g_num[t] = 0.0f; g_den[t] = 0.0f; }
}

// ---------------- NCHW f32 -> NHWC bf16x2 transpose (C=32), per batch ----------------
__global__ void transpose_bf16_kernel(const float* __restrict__ src, uint32_t* __restrict__ dst, int S) {
    __shared__ float t[32][33];
    int s0 = blockIdx.x * 32;
    const float* sb = src + (size_t)blockIdx.y * NC * S;
    uint32_t*    db = dst + (size_t)blockIdx.y * S * 16;
    int lx = threadIdx.x, ly = threadIdx.y;
    #pragma unroll
    for (int cc = 0; cc < 4; cc++) {
        int c = ly + cc * 8;
        t[c][lx] = sb[(size_t)c * S + s0 + lx];
    }
    __syncthreads();
    if (lx < 16) {
        #pragma unroll
        for (int cc = 0; cc < 4; cc++) {
            int sr = ly + cc * 8;
            db[(size_t)(s0 + sr) * 16 + lx] = pack_bf16(t[2*lx][sr], t[2*lx+1][sr]);
        }
    }
}

// ---------------- random pooling + sample-coordinate computation ----------------
__global__ void pool_kernel(const float* __restrict__ gts, const float* __restrict__ rnd) {
    int tid = blockIdx.x * blockDim.x + threadIdx.x;
    if (tid >= IT*NB*SH*SW) return;
    int x  = tid % SW;  int t1 = tid / SW;
    int y  = t1 % SH;   int t2 = t1 / SH;
    int b  = t2 % NB;   int it = t2 / NB;
    const float* gp = gts + b * GH * GW;
    const float* rp = rnd + (it * NB + b) * GH * GW;

    float best = -1.0f;
    int srow = y*4, scol = x*4;
    #pragma unroll
    for (int bi = 0; bi < 4; bi++) {
        int row = y*4 + bi;
        #pragma unroll
        for (int bj = 0; bj < 4; bj++) {
            int col = x*4 + bj;
            float g  = gp[row*GW + col];
            float rm = (g > 0.1f) ? rp[row*GW + col] : 0.0f;
            if (rm > best) { best = rm; srow = row; scol = col; }
        }
    }
    float rv = gp[srow*GW + scol];
    if (rv < 0.1f) rv = 0.0f;
    g_rg[tid] = rv;

    int index = srow*GW + scol + 1282;   // bias = 2 + 2*640
    float fx = (float)(index % GW);
    float fy = (float)(index / GW);
    float gx = 2.0f * (fx / (float)GW - 0.5f);
    float gy = 2.0f * (fy / (float)GH - 0.5f);
    g_ixb[tid] = (gx + 1.0f) * 0.5f * (float)(GW - 1);
    g_iyb[tid] = (gy + 1.0f) * 0.5f * (float)(GH - 1);
}

// ---------------- bilinear grid-sample, L2-reuse tiled ----------------
__global__ __launch_bounds__(256) void sample_kernel() {
    int b = blockIdx.z;
    int slot   = threadIdx.x >> 4;
    int lane16 = threadIdx.x & 15;
    const uint32_t* xb = g_xtb + (size_t)b * GH * GW * 16;

    #pragma unroll 1
    for (int r = 0; r < 160; r++) {
        int idx = r*16 + slot;
        int it = idx >> 7;
        int p  = idx & 127;
        int py = p >> 4, px = p & 15;
        int gy = blockIdx.y*8 + py, gx = blockIdx.x*16 + px;
        int pid = ((it*NB + b)*SH + gy)*SW + gx;

        float ix = g_ixb[pid], iy = g_iyb[pid];
        float x0f = floorf(ix), y0f = floorf(iy);
        float wx = ix - x0f, wy = iy - y0f;
        int x0 = (int)x0f, y0 = (int)y0f;

        float acc0 = 0.0f, acc1 = 0.0f;
#define CORNER(XC, YC, WG) {                                                \
            int xc = (XC), yc = (YC);                                       \
            bool v = (xc >= 0) && (xc <= GW-1) && (yc >= 0) && (yc <= GH-1);\
            int xi = min(max(xc, 0), GW-1);                                 \
            int yi = min(max(yc, 0), GH-1);                                 \
            float2 val = unpack_bf16(xb[(yi*GW + xi)*16 + lane16]);         \
            float w = (v ? (WG) : 0.0f);                                    \
            acc0 += val.x * w;                                              \
            acc1 += val.y * w;                                              \
        }
        CORNER(x0,   y0,   (1.0f-wx)*(1.0f-wy));
        CORNER(x0+1, y0,   wx*(1.0f-wy));
        CORNER(x0,   y0+1, (1.0f-wx)*wy);
        CORNER(x0+1, y0+1, wx*wy);
#undef CORNER
        g_feat[(size_t)pid*16 + lane16] = pack_bf16(acc0, acc1);
    }
}

// ---------------- conv3x3 (32->32) via HMMA + sigmoid*d -> attd (bf16) ----------------
// block = 8 rows x 32 px. warp w owns 64 px (m-tiles 4w..4w+3) x ALL 32 co:
// A fragments loaded once per warp (no cross-warp duplication); B register-preloaded per k-half.
#define PXS 80                                     // pixel record stride in bytes (32 bf16 + pad)
__global__ __launch_bounds__(128) void conv_att_kernel(const float* __restrict__ Watt,
                                                       const float* __restrict__ batt) {
    __shared__ __align__(16) char s_tile[10*34*PXS];          // 27200 B, im2col window
    __shared__ __align__(16) __nv_bfloat16 s_w[32][296];      // k-major weights

    int tid = threadIdx.x;
    int wid = tid >> 5, lane = tid & 31;
    int bx = blockIdx.x, by = blockIdx.y, z = blockIdx.z;

    const uint32_t* fz = g_feat + (size_t)z * SH * SW * 16;
    int gy0 = by*8 - 1, gx0 = bx*32 - 1;
    for (int idx = tid; idx < 10*34*16; idx += 128) {
        int w = idx & 15; int rem = idx >> 4;
        int xx = rem % 34; int yy = rem / 34;
        int ggy = gy0 + yy, ggx = gx0 + xx;
        uint32_t v = 0;
        if (ggy >= 0 && ggy < SH && ggx >= 0 && ggx < SW)
            v = fz[(ggy*SW + ggx)*16 + w];
        *(uint32_t*)(s_tile + (yy*34 + xx)*PXS + w*4) = v;
    }
    for (int idx = tid; idx < 32*288; idx += 128) {
        int co = idx / 288; int k = idx - co*288;
        int tap = k >> 5, ci = k & 31;
        s_w[co][k] = __float2bfloat16(Watt[(co*32 + ci)*9 + tap]);
    }
    __syncthreads();

    int g  = lane >> 2, t2 = lane & 3;
    int m_row = (lane & 7) + ((lane & 8) ? 8 : 0);
    uint32_t k8 = (lane & 16) ? 16u : 0u;
    uint32_t tb = smem_to_u32(s_tile);
    int b = z & 3;

    float acc[4][4][4];                    // [mt][cog][frag]
    #pragma unroll
    for (int mt = 0; mt < 4; mt++)
        #pragma unroll
        for (int cg = 0; cg < 4; cg++)
            #pragma unroll
            for (int i = 0; i < 4; i++) acc[mt][cg][i] = 0.0f;

    #pragma unroll
    for (int kh = 0; kh < 2; kh++) {
        // B fragments for this k-half: 9 taps x 4 co-groups x 2 regs
        uint32_t bfr[9][4][2];
        #pragma unroll
        for (int t = 0; t < 9; t++) {
            int k0 = (t*2 + kh)*16 + t2*2;
            #pragma unroll
            for (int cg = 0; cg < 4; cg++) {
                bfr[t][cg][0] = *(const uint32_t*)&s_w[cg*8 + g][k0];
                bfr[t][cg][1] = *(const uint32_t*)&s_w[cg*8 + g][k0 + 8];
            }
        }
        #pragma unroll
        for (int mt = 0; mt < 4; mt++) {
            int p0 = wid*64 + mt*16 + m_row;
            uint32_t abase = tb + (uint32_t)(((p0 >> 5)*34 + (p0 & 31))*PXS) + k8 + kh*32;
            #pragma unroll
            for (int t = 0; t < 9; t++) {
                uint32_t toff = (uint32_t)(((t/3)*34 + (t%3))*PXS);
                uint32_t A[4];
                ldmatrix_x4(A, abase + toff);
                #pragma unroll
                for (int cg = 0; cg < 4; cg++)
                    mma_bf16(acc[mt][cg], A, bfr[t][cg]);
            }
        }
    }

    // ---- epilogue: bias + sigmoid + *d -> g_attd (bf16x2) ----
    float2 bt[4];
    #pragma unroll
    for (int cg = 0; cg < 4; cg++) {
        bt[cg].x = batt[cg*8 + t2*2];
        bt[cg].y = batt[cg*8 + t2*2 + 1];
    }
    const uint32_t* db = g_dtb + (size_t)b * SH * SW * 16;
    uint32_t* ab = g_attd + (size_t)z * SH * SW * 16;
    #pragma unroll
    for (int mt = 0; mt < 4; mt++) {
        #pragma unroll
        for (int rr = 0; rr < 2; rr++) {
            int p = wid*64 + mt*16 + g + rr*8;
            int gy = by*8 + (p >> 5);
            int gx = bx*32 + (p & 31);
            size_t pxo = (size_t)(gy*SW + gx)*16;
            #pragma unroll
            for (int cg = 0; cg < 4; cg++) {
                float2 dv = unpack_bf16(db[pxo + cg*4 + t2]);
                float v0 = acc[mt][cg][rr*2+0] + bt[cg].x;
                float v1 = acc[mt][cg][rr*2+1] + bt[cg].y;
                float a0 = dv.x / (1.0f + __expf(-v0));
                float a1 = dv.y / (1.0f + __expf(-v1));
                ab[pxo + cg*4 + t2] = pack_bf16(a0, a1);
            }
        }
    }
}

// ---------------- conv3x3 (32->4) via HMMA + log-grads + masked smooth-L1 + reduction ----------------
__global__ __launch_bounds__(128) void conv_post_loss_kernel(const float* __restrict__ Wp,
                                                             const float* __restrict__ bp) {
    __shared__ __align__(16) char s_tile[10*34*PXS];
    __shared__ __align__(16) __nv_bfloat16 s_wp[8][296];
    __shared__ float s_ds[256][4];
    __shared__ float rnum[128];
    __shared__ float rden[128];

    int tid = threadIdx.x;
    int wid = tid >> 5, lane = tid & 31;
    int bx = blockIdx.x, by = blockIdx.y, z = blockIdx.z;

    const uint32_t* az = g_attd + (size_t)z * SH * SW * 16;
    int gy0 = by*8 - 1, gx0 = bx*32 - 1;
    for (int idx = tid; idx < 10*34*16; idx += 128) {
        int w = idx & 15; int rem = idx >> 4;
        int xx = rem % 34; int yy = rem / 34;
        int ggy = gy0 + yy, ggx = gx0 + xx;
        uint32_t v = 0;
        if (ggy >= 0 && ggy < SH && ggx >= 0 && ggx < SW)
            v = az[(ggy*SW + ggx)*16 + w];
        *(uint32_t*)(s_tile + (yy*34 + xx)*PXS + w*4) = v;
    }
    for (int idx = tid; idx < 8*288; idx += 128) {
        int co = idx / 288; int k = idx - co*288;
        int tap = k >> 5, ci = k & 31;
        s_wp[co][k] = (co < 4) ? __float2bfloat16(Wp[(co*32 + ci)*9 + tap])
                               : __float2bfloat16(0.0f);
    }
    __syncthreads();

    int g  = lane >> 2, t2 = lane & 3;
    uint32_t bf[18][2];
    #pragma unroll
    for (int j = 0; j < 18; j++) {
        int k0 = j*16 + t2*2;
        bf[j][0] = *(const uint32_t*)&s_wp[g][k0];
        bf[j][1] = *(const uint32_t*)&s_wp[g][k0 + 8];
    }

    int m_row = (lane & 7) + ((lane & 8) ? 8 : 0);
    uint32_t k8 = (lane & 16) ? 16u : 0u;
    uint32_t tb = smem_to_u32(s_tile);

    #pragma unroll 1
    for (int q = 0; q < 4; q++) {
        int mt = wid*4 + q;
        int p0 = mt*16 + m_row;
        uint32_t abase = tb + (uint32_t)(((p0 >> 5)*34 + (p0 & 31))*PXS) + k8;

        float acc[4] = {0,0,0,0};
        #pragma unroll
        for (int t = 0; t < 9; t++) {
            uint32_t toff = (uint32_t)(((t/3)*34 + (t%3))*PXS);
            #pragma unroll
            for (int h = 0; h < 2; h++) {
                uint32_t A[4];
                ldmatrix_x4(A, abase + toff + h*32);
                mma_bf16(acc, A, bf[t*2 + h]);
            }
        }
        if (t2 < 2) {
            int pA = mt*16 + g;
            int pB = pA + 8;
            s_ds[pA][t2*2+0] = acc[0];
            s_ds[pA][t2*2+1] = acc[1];
            s_ds[pB][t2*2+0] = acc[2];
            s_ds[pB][t2*2+1] = acc[3];
        }
    }
    __syncthreads();

    const float* rz = g_rg + z * SH * SW;
    const int dys[4] = {0, 1, 1, 1};
    const int dxs[4] = {1, 1, 0, -1};
    float num = 0.0f, den = 0.0f;
    #pragma unroll
    for (int pp = 0; pp < 2; pp++) {
        int p = tid + pp*128;
        int gy = by*8 + (p >> 5);
        int gx = bx*32 + (p & 31);
        float4 dsv = *(const float4*)&s_ds[p][0];
        float ds[4] = {dsv.x + bp[0], dsv.y + bp[1], dsv.z + bp[2], dsv.w + bp[3]};

        float rv = rz[gy*SW + gx];
        float lc = logf(rv + 1e-6f);
        bool  mc = rv > 0.1f;
        #pragma unroll
        for (int gI = 0; gI < 4; gI++) {
            int ny = gy + dys[gI], nx = gx + dxs[gI];
            bool inb = (ny < SH) && (nx >= 0) && (nx < SW);
            float nv = inb ? rz[ny*SW + nx] : 0.0f;
            float gg = lc - logf(nv + 1e-6f);
            float mk = (mc && (nv > 0.1f)) ? 1.0f : 0.0f;
            float a  = fabsf(ds[gI] - gg);
            float sl1 = (a < 0.01f) ? (0.5f * a * a / 0.01f) : (a - 0.005f);
            num += sl1 * mk;
            den += mk;
        }
    }
    rnum[tid] = num; rden[tid] = den;
    __syncthreads();
    for (int s = 64; s > 0; s >>= 1) {
        if (tid < s) { rnum[tid] += rnum[tid+s]; rden[tid] += rden[tid+s]; }
        __syncthreads();
    }
    if (tid == 0) {
        int it = z >> 2;
        atomicAdd(&g_num[it], rnum[0]);
        atomicAdd(&g_den[it], rden[0]);
    }
}

// ---------------- finalize: mean over iterations of num/den ----------------
__global__ void finalize_kernel(float* out) {
    if (threadIdx.x == 0 && blockIdx.x == 0) {
        float s = 0.0f;
        for (int i = 0; i < IT; i++) s += g_num[i] / g_den[i];
        out[0] = s / (float)IT;
    }
}

// ---------------- launch ----------------
extern "C" void kernel_launch(void* const* d_in, const int* in_sizes, int n_in,
                              void* d_out, int out_size) {
    const float* x    = (const float*)d_in[0];
    const float* d    = (const float*)d_in[1];
    const float* gts  = (const float*)d_in[2];
    const float* rnd  = (const float*)d_in[3];
    const float* Watt = (const float*)d_in[4];
    const float* batt = (const float*)d_in[5];
    const float* Wp   = (const float*)d_in[6];
    const float* bp   = (const float*)d_in[7];
    float* out = (float*)d_out;

    uint32_t *xtb, *dtb;
    cudaGetSymbolAddress((void**)&xtb, g_xtb);
    cudaGetSymbolAddress((void**)&dtb, g_dtb);

    zero_kernel<<<1, 32>>>();
    transpose_bf16_kernel<<<dim3(GH*GW/32, NB), dim3(32, 8)>>>(x, xtb, GH*GW);
    transpose_bf16_kernel<<<dim3(SH*SW/32, NB), dim3(32, 8)>>>(d, dtb, SH*SW);
    pool_kernel<<<(IT*NB*SH*SW + 255)/256, 256>>>(gts, rnd);
    sample_kernel<<<dim3(SW/16, SH/8, NB), 256>>>();
    conv_att_kernel<<<dim3(SW/32, SH/8, IT*NB), 128>>>(Watt, batt);
    conv_post_loss_kernel<<<dim3(SW/32, SH/8, IT*NB), 128>>>(Wp, bp);
    finalize_kernel<<<1, 32>>>(out);
}

// round 15
// speedup vs baseline: 1.1498x; 1.1498x over previous
#include <cuda_runtime.h>
#include <cuda_bf16.h>
#include <math.h>
#include <cstdint>

#define IT 20
#define NB 4
#define GH 480
#define GW 640
#define SH 120
#define SW 160
#define NC 32

typedef unsigned long long u64;

// ---------------- static device scratch (no runtime allocation) ----------------
__device__ uint32_t g_xtb[NB*GH*GW*16];             // x transposed to NHWC bf16x2 (78 MB)
__device__ uint32_t g_dtb[NB*SH*SW*16];             // d transposed to NHWC bf16x2 (4.9 MB)
__device__ float    g_rg[IT*NB*SH*SW];              // pooled gt
__device__ float    g_ixb[IT*NB*SH*SW];             // sample x pixel coord
__device__ float    g_iyb[IT*NB*SH*SW];             // sample y pixel coord
__device__ uint32_t g_feat[IT*NB*SH*SW*16];         // sampled features NHWC bf16x2 (98 MB)
__device__ uint32_t g_attd[IT*NB*SH*SW*16];         // sigmoid(conv)*d NHWC bf16x2  (98 MB)
__device__ __align__(16) __nv_bfloat16 g_wat[32*296];  // pre-converted att weights (k-major, padded)
__device__ __align__(16) __nv_bfloat16 g_wpp[8*296];   // pre-converted post weights (rows 4..7 zero)
__device__ float    g_num[IT];
__device__ float    g_den[IT];

// ---------------- helpers ----------------
__device__ __forceinline__ uint32_t pack_bf16(float lo, float hi) {
    uint32_t r;
    asm("cvt.rn.bf16x2.f32 %0, %1, %2;" : "=r"(r) : "f"(hi), "f"(lo));
    return r;
}
__device__ __forceinline__ float2 unpack_bf16(uint32_t u) {
    __nv_bfloat162 h = *reinterpret_cast<const __nv_bfloat162*>(&u);
    return make_float2(__bfloat162float(h.x), __bfloat162float(h.y));
}
__device__ __forceinline__ uint32_t smem_to_u32(const void* p) {
    uint32_t a;
    asm("{ .reg .u64 t; cvta.to.shared.u64 t, %1; cvt.u32.u64 %0, t; }" : "=r"(a) : "l"(p));
    return a;
}
__device__ __forceinline__ void ldmatrix_x4(uint32_t* r, uint32_t addr) {
    asm volatile("ldmatrix.sync.aligned.m8n8.x4.shared.b16 {%0, %1, %2, %3}, [%4];"
        : "=r"(r[0]), "=r"(r[1]), "=r"(r[2]), "=r"(r[3]) : "r"(addr));
}
__device__ __forceinline__ void mma_bf16(float* c, const uint32_t* a, const uint32_t* b) {
    asm volatile("mma.sync.aligned.m16n8k16.row.col.f32.bf16.bf16.f32 "
        "{%0, %1, %2, %3}, {%4, %5, %6, %7}, {%8, %9}, {%0, %1, %2, %3};"
        : "+f"(c[0]), "+f"(c[1]), "+f"(c[2]), "+f"(c[3])
        : "r"(a[0]), "r"(a[1]), "r"(a[2]), "r"(a[3]), "r"(b[0]), "r"(b[1]));
}

// ---------------- zero accumulators + pre-convert weights ----------------
__global__ void zero_kernel() {
    int t = threadIdx.x;
    if (t < IT) { g_num[t] = 0.0f; g_den[t] = 0.0f; }
}
__global__ void prep_weights_kernel(const float* __restrict__ Watt, const float* __restrict__ Wp) {
    int tid = blockIdx.x * 256 + threadIdx.x;          // 0..9471
    if (tid < 32*296) {
        int co = tid / 296; int k = tid - co*296;
        __nv_bfloat16 v = __float2bfloat16(0.0f);
        if (k < 288) {
            int tap = k >> 5, ci = k & 31;
            v = __float2bfloat16(Watt[(co*32 + ci)*9 + tap]);
        }
        g_wat[tid] = v;
    }
    if (tid < 8*296) {
        int co = tid / 296; int k = tid - co*296;
        __nv_bfloat16 v = __float2bfloat16(0.0f);
        if (k < 288 && co < 4) {
            int tap = k >> 5, ci = k & 31;
            v = __float2bfloat16(Wp[(co*32 + ci)*9 + tap]);
        }
        g_wpp[tid] = v;
    }
}

// ---------------- NCHW f32 -> NHWC bf16x2 transpose (C=32), per batch ----------------
__global__ void transpose_bf16_kernel(const float* __restrict__ src, uint32_t* __restrict__ dst, int S) {
    __shared__ float t[32][33];
    int s0 = blockIdx.x * 32;
    const float* sb = src + (size_t)blockIdx.y * NC * S;
    uint32_t*    db = dst + (size_t)blockIdx.y * S * 16;
    int lx = threadIdx.x, ly = threadIdx.y;
    #pragma unroll
    for (int cc = 0; cc < 4; cc++) {
        int c = ly + cc * 8;
        t[c][lx] = sb[(size_t)c * S + s0 + lx];
    }
    __syncthreads();
    if (lx < 16) {
        #pragma unroll
        for (int cc = 0; cc < 4; cc++) {
            int sr = ly + cc * 8;
            db[(size_t)(s0 + sr) * 16 + lx] = pack_bf16(t[2*lx][sr], t[2*lx+1][sr]);
        }
    }
}

// ---------------- random pooling + sample-coordinate computation (float4 loads) ----------------
__global__ void pool_kernel(const float* __restrict__ gts, const float* __restrict__ rnd) {
    int tid = blockIdx.x * blockDim.x + threadIdx.x;
    if (tid >= IT*NB*SH*SW) return;
    int x  = tid % SW;  int t1 = tid / SW;
    int y  = t1 % SH;   int t2 = t1 / SH;
    int b  = t2 % NB;   int it = t2 / NB;
    const float* gp = gts + b * GH * GW;
    const float* rp = rnd + (it * NB + b) * GH * GW;

    float best = -1.0f;
    int srow = y*4, scol = x*4;
    float bestg = 0.0f;
    #pragma unroll
    for (int bi = 0; bi < 4; bi++) {
        int row = y*4 + bi;
        float4 g4 = *(const float4*)&gp[row*GW + x*4];
        float4 r4 = *(const float4*)&rp[row*GW + x*4];
        float gv[4] = {g4.x, g4.y, g4.z, g4.w};
        float rv[4] = {r4.x, r4.y, r4.z, r4.w};
        #pragma unroll
        for (int bj = 0; bj < 4; bj++) {
            float rm = (gv[bj] > 0.1f) ? rv[bj] : 0.0f;
            if (rm > best) { best = rm; srow = row; scol = x*4 + bj; bestg = gv[bj]; }
        }
    }
    float rv = (bestg < 0.1f) ? 0.0f : bestg;
    g_rg[tid] = rv;

    int index = srow*GW + scol + 1282;   // bias = 2 + 2*640
    float fx = (float)(index % GW);
    float fy = (float)(index / GW);
    float gx = 2.0f * (fx / (float)GW - 0.5f);
    float gy = 2.0f * (fy / (float)GH - 0.5f);
    g_ixb[tid] = (gx + 1.0f) * 0.5f * (float)(GW - 1);
    g_iyb[tid] = (gy + 1.0f) * 0.5f * (float)(GH - 1);
}

// ---------------- bilinear grid-sample, L2-reuse tiled ----------------
__global__ __launch_bounds__(256) void sample_kernel() {
    int b = blockIdx.z;
    int slot   = threadIdx.x >> 4;
    int lane16 = threadIdx.x & 15;
    const uint32_t* xb = g_xtb + (size_t)b * GH * GW * 16;

    #pragma unroll 1
    for (int r = 0; r < 160; r++) {
        int idx = r*16 + slot;
        int it = idx >> 7;
        int p  = idx & 127;
        int py = p >> 4, px = p & 15;
        int gy = blockIdx.y*8 + py, gx = blockIdx.x*16 + px;
        int pid = ((it*NB + b)*SH + gy)*SW + gx;

        float ix = g_ixb[pid], iy = g_iyb[pid];
        float x0f = floorf(ix), y0f = floorf(iy);
        float wx = ix - x0f, wy = iy - y0f;
        int x0 = (int)x0f, y0 = (int)y0f;

        float acc0 = 0.0f, acc1 = 0.0f;
#define CORNER(XC, YC, WG) {                                                \
            int xc = (XC), yc = (YC);                                       \
            bool v = (xc >= 0) && (xc <= GW-1) && (yc >= 0) && (yc <= GH-1);\
            int xi = min(max(xc, 0), GW-1);                                 \
            int yi = min(max(yc, 0), GH-1);                                 \
            float2 val = unpack_bf16(xb[(yi*GW + xi)*16 + lane16]);         \
            float w = (v ? (WG) : 0.0f);                                    \
            acc0 += val.x * w;                                              \
            acc1 += val.y * w;                                              \
        }
        CORNER(x0,   y0,   (1.0f-wx)*(1.0f-wy));
        CORNER(x0+1, y0,   wx*(1.0f-wy));
        CORNER(x0,   y0+1, (1.0f-wx)*wy);
        CORNER(x0+1, y0+1, wx*wy);
#undef CORNER
        g_feat[(size_t)pid*16 + lane16] = pack_bf16(acc0, acc1);
    }
}

// ---------------- conv3x3 (32->32) via HMMA + sigmoid*d -> attd (bf16) ----------------
// R13 warp mapping: warp w owns co-tile [w*8, w*8+8) over all 256 px.
// Tile + weight loads fully vectorized (uint4).
#define PXS 80                                     // pixel record stride in bytes (32 bf16 + pad)
__global__ __launch_bounds__(128) void conv_att_kernel(const float* __restrict__ batt) {
    __shared__ __align__(16) char s_tile[10*34*PXS];          // 27200 B, im2col window
    __shared__ __align__(16) __nv_bfloat16 s_w[32][296];      // k-major weights

    int tid = threadIdx.x;
    int wid = tid >> 5, lane = tid & 31;
    int bx = blockIdx.x, by = blockIdx.y, z = blockIdx.z;

    // ---- feat window: uint4 loads (4 u32 words each) ----
    const uint32_t* fz = g_feat + (size_t)z * SH * SW * 16;
    int gy0 = by*8 - 1, gx0 = bx*32 - 1;
    for (int idx = tid; idx < 10*34*4; idx += 128) {
        int w4 = idx & 3; int rem = idx >> 2;
        int xx = rem % 34; int yy = rem / 34;
        int ggy = gy0 + yy, ggx = gx0 + xx;
        uint4 v = make_uint4(0u, 0u, 0u, 0u);
        if (ggy >= 0 && ggy < SH && ggx >= 0 && ggx < SW)
            v = ((const uint4*)&fz[(ggy*SW + ggx)*16])[w4];
        *(uint4*)(s_tile + (yy*34 + xx)*PXS + w4*16) = v;
    }
    // ---- weights: straight uint4 copy of pre-converted layout ----
    {
        const uint4* wsrc = (const uint4*)g_wat;
        uint4* wdst = (uint4*)&s_w[0][0];
        for (int i = tid; i < 32*296/8; i += 128) wdst[i] = wsrc[i];
    }
    __syncthreads();

    int g  = lane >> 2, t2 = lane & 3;
    uint32_t bf[18][2];
    #pragma unroll
    for (int j = 0; j < 18; j++) {
        int k0 = j*16 + t2*2;
        bf[j][0] = *(const uint32_t*)&s_w[wid*8 + g][k0];
        bf[j][1] = *(const uint32_t*)&s_w[wid*8 + g][k0 + 8];
    }

    int m_row = (lane & 7) + ((lane & 8) ? 8 : 0);
    uint32_t k8 = (lane & 16) ? 16u : 0u;
    uint32_t tb = smem_to_u32(s_tile);
    int b = z & 3;
    int co0 = wid*8 + t2*2;
    float bt0 = batt[co0], bt1 = batt[co0+1];
    const uint32_t* db = g_dtb + (size_t)b * SH * SW * 16;
    uint32_t* ab = g_attd + (size_t)z * SH * SW * 16;

    #pragma unroll 1
    for (int mp = 0; mp < 8; mp++) {
        int p0 = mp*32 + m_row;
        int p1 = p0 + 16;
        uint32_t a0base = tb + (uint32_t)(((p0 >> 5)*34 + (p0 & 31))*PXS) + k8;
        uint32_t a1base = tb + (uint32_t)(((p1 >> 5)*34 + (p1 & 31))*PXS) + k8;

        float acc0[4] = {0,0,0,0};
        float acc1[4] = {0,0,0,0};
        #pragma unroll
        for (int t = 0; t < 9; t++) {
            uint32_t toff = (uint32_t)(((t/3)*34 + (t%3))*PXS);
            #pragma unroll
            for (int h = 0; h < 2; h++) {
                int j = t*2 + h;
                uint32_t A0[4], A1[4];
                ldmatrix_x4(A0, a0base + toff + h*32);
                ldmatrix_x4(A1, a1base + toff + h*32);
                mma_bf16(acc0, A0, bf[j]);
                mma_bf16(acc1, A1, bf[j]);
            }
        }

        #pragma unroll
        for (int half = 0; half < 2; half++) {
            float* acc = half ? acc1 : acc0;
            int pb = mp*32 + half*16;
            #pragma unroll
            for (int r = 0; r < 2; r++) {
                int p = pb + g + r*8;
                int gy = by*8 + (p >> 5);
                int gx = bx*32 + (p & 31);
                size_t pxo = (size_t)(gy*SW + gx)*16;
                float2 dv = unpack_bf16(db[pxo + (co0 >> 1)]);
                float v0 = acc[r*2+0] + bt0;
                float v1 = acc[r*2+1] + bt1;
                float a0 = dv.x / (1.0f + __expf(-v0));
                float a1 = dv.y / (1.0f + __expf(-v1));
                ab[pxo + (co0 >> 1)] = pack_bf16(a0, a1);
            }
        }
    }
}

// ---------------- conv3x3 (32->4) via HMMA + log-grads + masked smooth-L1 + reduction ----------------
__global__ __launch_bounds__(128) void conv_post_loss_kernel(const float* __restrict__ bp) {
    __shared__ __align__(16) char s_tile[10*34*PXS];
    __shared__ __align__(16) __nv_bfloat16 s_wp[8][296];
    __shared__ float s_ds[256][4];
    __shared__ float rnum[128];
    __shared__ float rden[128];

    int tid = threadIdx.x;
    int wid = tid >> 5, lane = tid & 31;
    int bx = blockIdx.x, by = blockIdx.y, z = blockIdx.z;

    const uint32_t* az = g_attd + (size_t)z * SH * SW * 16;
    int gy0 = by*8 - 1, gx0 = bx*32 - 1;
    for (int idx = tid; idx < 10*34*4; idx += 128) {
        int w4 = idx & 3; int rem = idx >> 2;
        int xx = rem % 34; int yy = rem / 34;
        int ggy = gy0 + yy, ggx = gx0 + xx;
        uint4 v = make_uint4(0u, 0u, 0u, 0u);
        if (ggy >= 0 && ggy < SH && ggx >= 0 && ggx < SW)
            v = ((const uint4*)&az[(ggy*SW + ggx)*16])[w4];
        *(uint4*)(s_tile + (yy*34 + xx)*PXS + w4*16) = v;
    }
    {
        const uint4* wsrc = (const uint4*)g_wpp;
        uint4* wdst = (uint4*)&s_wp[0][0];
        for (int i = tid; i < 8*296/8; i += 128) wdst[i] = wsrc[i];
    }
    __syncthreads();

    int g  = lane >> 2, t2 = lane & 3;
    uint32_t bf[18][2];
    #pragma unroll
    for (int j = 0; j < 18; j++) {
        int k0 = j*16 + t2*2;
        bf[j][0] = *(const uint32_t*)&s_wp[g][k0];
        bf[j][1] = *(const uint32_t*)&s_wp[g][k0 + 8];
    }

    int m_row = (lane & 7) + ((lane & 8) ? 8 : 0);
    uint32_t k8 = (lane & 16) ? 16u : 0u;
    uint32_t tb = smem_to_u32(s_tile);

    #pragma unroll 1
    for (int q = 0; q < 4; q++) {
        int mt = wid*4 + q;
        int p0 = mt*16 + m_row;
        uint32_t abase = tb + (uint32_t)(((p0 >> 5)*34 + (p0 & 31))*PXS) + k8;

        float acc[4] = {0,0,0,0};
        #pragma unroll
        for (int t = 0; t < 9; t++) {
            uint32_t toff = (uint32_t)(((t/3)*34 + (t%3))*PXS);
            #pragma unroll
            for (int h = 0; h < 2; h++) {
                uint32_t A[4];
                ldmatrix_x4(A, abase + toff + h*32);
                mma_bf16(acc, A, bf[t*2 + h]);
            }
        }
        if (t2 < 2) {
            int pA = mt*16 + g;
            int pB = pA + 8;
            s_ds[pA][t2*2+0] = acc[0];
            s_ds[pA][t2*2+1] = acc[1];
            s_ds[pB][t2*2+0] = acc[2];
            s_ds[pB][t2*2+1] = acc[3];
        }
    }
    __syncthreads();

    const float* rz = g_rg + z * SH * SW;
    const int dys[4] = {0, 1, 1, 1};
    const int dxs[4] = {1, 1, 0, -1};
    float num = 0.0f, den = 0.0f;
    #pragma unroll
    for (int pp = 0; pp < 2; pp++) {
        int p = tid + pp*128;
        int gy = by*8 + (p >> 5);
        int gx = bx*32 + (p & 31);
        float4 dsv = *(const float4*)&s_ds[p][0];
        float ds[4] = {dsv.x + bp[0], dsv.y + bp[1], dsv.z + bp[2], dsv.w + bp[3]};

        float rv = rz[gy*SW + gx];
        float lc = logf(rv + 1e-6f);
        bool  mc = rv > 0.1f;
        #pragma unroll
        for (int gI = 0; gI < 4; gI++) {
            int ny = gy + dys[gI], nx = gx + dxs[gI];
            bool inb = (ny < SH) && (nx >= 0) && (nx < SW);
            float nv = inb ? rz[ny*SW + nx] : 0.0f;
            float gg = lc - logf(nv + 1e-6f);
            float mk = (mc && (nv > 0.1f)) ? 1.0f : 0.0f;
            float a  = fabsf(ds[gI] - gg);
            float sl1 = (a < 0.01f) ? (0.5f * a * a / 0.01f) : (a - 0.005f);
            num += sl1 * mk;
            den += mk;
        }
    }
    rnum[tid] = num; rden[tid] = den;
    __syncthreads();
    for (int s = 64; s > 0; s >>= 1) {
        if (tid < s) { rnum[tid] += rnum[tid+s]; rden[tid] += rden[tid+s]; }
        __syncthreads();
    }
    if (tid == 0) {
        int it = z >> 2;
        atomicAdd(&g_num[it], rnum[0]);
        atomicAdd(&g_den[it], rden[0]);
    }
}

// ---------------- finalize: mean over iterations of num/den ----------------
__global__ void finalize_kernel(float* out) {
    if (threadIdx.x == 0 && blockIdx.x == 0) {
        float s = 0.0f;
        for (int i = 0; i < IT; i++) s += g_num[i] / g_den[i];
        out[0] = s / (float)IT;
    }
}

// ---------------- launch ----------------
extern "C" void kernel_launch(void* const* d_in, const int* in_sizes, int n_in,
                              void* d_out, int out_size) {
    const float* x    = (const float*)d_in[0];
    const float* d    = (const float*)d_in[1];
    const float* gts  = (const float*)d_in[2];
    const float* rnd  = (const float*)d_in[3];
    const float* Watt = (const float*)d_in[4];
    const float* batt = (const float*)d_in[5];
    const float* Wp   = (const float*)d_in[6];
    const float* bp   = (const float*)d_in[7];
    float* out = (float*)d_out;

    uint32_t *xtb, *dtb;
    cudaGetSymbolAddress((void**)&xtb, g_xtb);
    cudaGetSymbolAddress((void**)&dtb, g_dtb);

    zero_kernel<<<1, 32>>>();
    prep_weights_kernel<<<37, 256>>>(Watt, Wp);
    transpose_bf16_kernel<<<dim3(GH*GW/32, NB), dim3(32, 8)>>>(x, xtb, GH*GW);
    transpose_bf16_kernel<<<dim3(SH*SW/32, NB), dim3(32, 8)>>>(d, dtb, SH*SW);
    pool_kernel<<<(IT*NB*SH*SW + 255)/256, 256>>>(gts, rnd);
    sample_kernel<<<dim3(SW/16, SH/8, NB), 256>>>();
    conv_att_kernel<<<dim3(SW/32, SH/8, IT*NB), 128>>>(batt);
    conv_post_loss_kernel<<<dim3(SW/32, SH/8, IT*NB), 128>>>(bp);
    finalize_kernel<<<1, 32>>>(out);
}